// round 1
// baseline (speedup 1.0000x reference)
#include <cuda_runtime.h>
#include <math.h>

// LundWeight reweighting.
// Shapes: z (B=8192, M=128, K=25) f32, mT (B,128) f32, observable (B,2) i64 (UNUSED:
// setup guarantees z==0 exactly where mask would be false), params_a (1), params_b (1),
// params_base (2). Output: (B,) f32.

#define EXPMAX 50.0f
#define OSF    15.0f

__device__ __forceinline__ float zmax_calc(float a, float b) {
    const float c = 1.0f;
    if (a < 0.02f) return (c > b) ? b : 1.0f;              // b/c with c=1
    if (fabsf(a - c) < 0.01f) return b / (b + c);
    float z = 0.5f * (b + c - sqrtf((b - c) * (b - c) + 4.0f * a * b)) / (c - a);
    if (z > 0.9999f && b > 100.0f) z = fminf(z, 1.0f - a / b);
    return z;
}

__global__ __launch_bounds__(256, 8) void lund_weight_kernel(
    const float* __restrict__ Z,      // (B,128,25)
    const float* __restrict__ MT,     // (B,128)
    const float* __restrict__ p_a,    // (1,)
    const float* __restrict__ p_b,    // (1,)
    const float* __restrict__ p_base, // (2,)
    float* __restrict__ out)          // (B,)
{
    __shared__ float sBe[2][128];   // b_exp per (set, m)
    __shared__ float sC [2][128];   // z-independent constant per (set, m)
    __shared__ float sRed[8];

    const int b   = blockIdx.x;
    const int tid = threadIdx.x;

    const float aP = p_a[0],    bP = p_b[0];
    const float a0 = p_base[0], b0 = p_base[1];
    const float aUP = (aP < 0.02f) ? 0.0f : aP;   // a-coef dropped when a ~ 0
    const float aU0 = (a0 < 0.02f) ? 0.0f : a0;

    // ---- Phase 1: per-(m, param_set) constants. 256 threads = 2 sets x 128 m. ----
    {
        const int set = tid >> 7;         // 0 = fit params, 1 = base params
        const int m   = tid & 127;
        const float a    = set ? a0  : aP;
        const float bpar = set ? b0  : bP;
        const float aU   = set ? aU0 : aUP;
        const float mt = MT[b * 128 + m];
        const float be = bpar * mt * mt;            // b_exp
        const float zm = zmax_calc(a, be);
        float C = be / zm + logf(zm);               // precise math here (cheap: 2M total)
        if (aU != 0.0f) C -= aU * logf(1.0f - zm);  // guard 0 * (-inf) when zm == 1
        sBe[set][m] = be;
        sC [set][m] = C;
    }
    __syncthreads();

    // ---- Phase 2: 3200 elements per batch; f(z) = C - be/z - ln z + aU*ln(1-z). ----
    const float* __restrict__ zrow = Z + (size_t)b * 3200;
    float prod = 1.0f;

    #pragma unroll 1
    for (int k = 0; k < 13; ++k) {                  // 13 * 256 >= 3200, uniform trip count
        const int idx = tid + (k << 8);
        const bool inr = idx < 3200;
        const float z = inr ? zrow[idx] : 0.0f;
        const bool act = inr && (z != 0.0f);
        // whole-warp skip: the invalid (m >= mult) tail is contiguous zeros (~40%)
        if (__ballot_sync(0xffffffffu, act) == 0u) continue;
        if (act) {
            const int m = idx / 25;
            const bool accq = (idx - m * 25) == 0;  // r == 0 -> accepted-emission weight

            const float rz  = __fdividef(1.0f, z);  // MUFU.RCP — shared across both sets
            const float lz  = __logf(z);            // MUFU.LG2 — shared
            const float l1z = __logf(1.0f - z);     // MUFU.LG2 — shared

            float fP = sC[0][m] - sBe[0][m] * rz - lz + aUP * l1z;
            float f0 = sC[1][m] - sBe[1][m] * rz - lz + aU0 * l1z;
            fP = fminf(fmaxf(fP, -EXPMAX), EXPMAX);
            f0 = fminf(fmaxf(f0, -EXPMAX), EXPMAX);
            const float eP = __expf(fP);
            const float e0 = __expf(f0);

            const float num = accq ? eP : (OSF - eP);
            const float den = accq ? e0 : (OSF - e0);
            prod *= __fdividef(num, den);
        }
    }

    // ---- Phase 3: block product reduction ----
    #pragma unroll
    for (int off = 16; off; off >>= 1)
        prod *= __shfl_xor_sync(0xffffffffu, prod, off);
    if ((tid & 31) == 0) sRed[tid >> 5] = prod;
    __syncthreads();
    if (tid < 32) {
        float p = (tid < 8) ? sRed[tid] : 1.0f;
        #pragma unroll
        for (int off = 4; off; off >>= 1)
            p *= __shfl_xor_sync(0xffffffffu, p, off);
        if (tid == 0) out[b] = p;
    }
}

extern "C" void kernel_launch(void* const* d_in, const int* in_sizes, int n_in,
                              void* d_out, int out_size) {
    const float* Z      = (const float*)d_in[0];
    const float* MT     = (const float*)d_in[1];
    // d_in[2] = observable (int64) — intentionally unused: z==0 encodes the mask.
    const float* p_a    = (const float*)d_in[3];
    const float* p_b    = (const float*)d_in[4];
    const float* p_base = (const float*)d_in[5];
    float* out = (float*)d_out;

    const int B = out_size;   // 8192
    lund_weight_kernel<<<B, 256>>>(Z, MT, p_a, p_b, p_base, out);
}

// round 2
// speedup vs baseline: 1.2227x; 1.2227x over previous
#include <cuda_runtime.h>
#include <math.h>

// LundWeight reweighting, compaction strategy.
// z (8192,128,25) f32; mT (8192,128) f32; observable unused (z==0 encodes mask);
// params_a, params_b, params_base. Output (8192,) f32.

#define EXPMAX 50.0f
#define OSF    15.0f

__device__ __forceinline__ float zmax_calc(float a, float b) {
    const float c = 1.0f;
    if (a < 0.02f) return (c > b) ? b : 1.0f;
    if (fabsf(a - c) < 0.01f) return b / (b + c);
    float z = 0.5f * (b + c - sqrtf((b - c) * (b - c) + 4.0f * a * b)) / (c - a);
    if (z > 0.9999f && b > 100.0f) z = fminf(z, 1.0f - a / b);
    return z;
}

__global__ __launch_bounds__(256, 8) void lund_weight_kernel(
    const float4* __restrict__ Z4,    // (B,800) float4 view of (B,128,25)
    const float* __restrict__ MT,     // (B,128)
    const float* __restrict__ p_a,
    const float* __restrict__ p_b,
    const float* __restrict__ p_base,
    float* __restrict__ out)          // (B,)
{
    __shared__ float4 sK[128];               // {beP, CP, be0, C0} per m
    __shared__ float  sZ[3200];              // compacted active z
    __shared__ unsigned short sMeta[3200];   // compacted flat idx (m*25+r)
    __shared__ int   sCnt;
    __shared__ float sRed[8];

    const int b   = blockIdx.x;
    const int tid = threadIdx.x;
    const int lane = tid & 31;
    if (tid == 0) sCnt = 0;

    const float aP = p_a[0],    bP = p_b[0];
    const float a0 = p_base[0], b0 = p_base[1];
    const float aUP = (aP < 0.02f) ? 0.0f : aP;
    const float aU0 = (a0 < 0.02f) ? 0.0f : a0;

    // ---- Phase 1: per-m constants, both param sets, packed into one float4 ----
    if (tid < 128) {
        const float mt  = MT[b * 128 + tid];
        const float mt2 = mt * mt;
        const float beP = bP * mt2;
        const float zmP = zmax_calc(aP, beP);
        float CP = beP / zmP + logf(zmP);
        if (aUP != 0.0f) CP -= aUP * logf(1.0f - zmP);
        const float be0 = b0 * mt2;
        const float zm0 = zmax_calc(a0, be0);
        float C0 = be0 / zm0 + logf(zm0);
        if (aU0 != 0.0f) C0 -= aU0 * logf(1.0f - zm0);
        sK[tid] = make_float4(beP, CP, be0, C0);
    }
    __syncthreads();

    // ---- Phase 2: vectorized load + warp-aggregated compaction of active z ----
    const float4* __restrict__ zr = Z4 + (size_t)b * 800;
    #pragma unroll 1
    for (int k = 0; k < 4; ++k) {
        const int g = tid + (k << 8);                 // float4 index < 800
        float4 v = make_float4(0.f, 0.f, 0.f, 0.f);
        if (g < 800) v = zr[g];
        const float zz[4] = {v.x, v.y, v.z, v.w};
        #pragma unroll
        for (int j = 0; j < 4; ++j) {
            const bool act = (zz[j] != 0.0f);
            const unsigned mask = __ballot_sync(0xffffffffu, act);
            if (mask) {
                int base;
                if (lane == 0) base = atomicAdd(&sCnt, __popc(mask));
                base = __shfl_sync(0xffffffffu, base, 0);
                if (act) {
                    const int pos = base + __popc(mask & ((1u << lane) - 1u));
                    sZ[pos]    = zz[j];
                    sMeta[pos] = (unsigned short)(g * 4 + j);
                }
            }
        }
    }
    __syncthreads();
    const int n = sCnt;

    // ---- Phase 3: dense math over active elements only ----
    float prod = 1.0f;
    #pragma unroll 1
    for (int i = tid; i < n; i += 256) {
        const float z   = sZ[i];
        const int   idx = sMeta[i];
        const int   m   = (idx * 5243) >> 17;         // exact idx/25 for idx<3200
        const bool accq = (idx - m * 25) == 0;
        const float4 kk = sK[m];

        const float rz  = __fdividef(1.0f, z);
        const float lz  = __logf(z);
        const float l1z = __logf(1.0f - z);

        float fP = kk.y - kk.x * rz - lz + aUP * l1z;
        float f0 = kk.w - kk.z * rz - lz + aU0 * l1z;
        fP = fminf(fmaxf(fP, -EXPMAX), EXPMAX);
        f0 = fminf(fmaxf(f0, -EXPMAX), EXPMAX);
        const float eP = __expf(fP);
        const float e0 = __expf(f0);

        const float num = accq ? eP : (OSF - eP);
        const float den = accq ? e0 : (OSF - e0);
        prod *= __fdividef(num, den);
    }

    // ---- Phase 4: block product reduction ----
    #pragma unroll
    for (int off = 16; off; off >>= 1)
        prod *= __shfl_xor_sync(0xffffffffu, prod, off);
    if (lane == 0) sRed[tid >> 5] = prod;
    __syncthreads();
    if (tid < 32) {
        float p = (tid < 8) ? sRed[tid] : 1.0f;
        #pragma unroll
        for (int off = 4; off; off >>= 1)
            p *= __shfl_xor_sync(0xffffffffu, p, off);
        if (tid == 0) out[b] = p;
    }
}

extern "C" void kernel_launch(void* const* d_in, const int* in_sizes, int n_in,
                              void* d_out, int out_size) {
    const float4* Z4    = (const float4*)d_in[0];
    const float*  MT    = (const float*)d_in[1];
    // d_in[2] observable: unused (z==0 encodes the mask exactly).
    const float*  p_a   = (const float*)d_in[3];
    const float*  p_b   = (const float*)d_in[4];
    const float*  p_base= (const float*)d_in[5];
    float* out = (float*)d_out;

    const int B = out_size;   // 8192
    lund_weight_kernel<<<B, 256>>>(Z4, MT, p_a, p_b, p_base, out);
}

// round 5
// speedup vs baseline: 1.6776x; 1.3721x over previous
#include <cuda_runtime.h>
#include <math.h>

// LundWeight reweighting, round 5: R4 with the log2-domain a-coefficient fixed.
// a*ln(x) == a*lg2(x)*ln2, so after multiplying f by LOG2E the lg2-term
// coefficient is plain `a` (R4 wrongly used a*LOG2E -> 10% rel_err).
// z (8192,128,25) f32; mT (8192,128) f32; observable (8192,2) i32 (mult=[:,0]);
// params_a, params_b, params_base. Output (8192,) f32.

#define LOG2E 1.4426950408889634f
#define F2MIN (-72.13475f)  /* -50 * LOG2E : lower clip in log2 domain */
#define OSF   15.0f

__device__ __forceinline__ float rcp_fast(float x){ float r; asm("rcp.approx.f32 %0,%1;":"=f"(r):"f"(x)); return r; }
__device__ __forceinline__ float lg2_fast(float x){ float r; asm("lg2.approx.f32 %0,%1;":"=f"(r):"f"(x)); return r; }
__device__ __forceinline__ float ex2_fast(float x){ float r; asm("ex2.approx.f32 %0,%1;":"=f"(r):"f"(x)); return r; }

__device__ __forceinline__ float zmax_calc(float a, float b) {
    const float c = 1.0f;
    if (a < 0.02f) return (c > b) ? b : 1.0f;
    if (fabsf(a - c) < 0.01f) return b / (b + c);
    float z = 0.5f * (b + c - sqrtf((b - c) * (b - c) + 4.0f * a * b)) / (c - a);
    if (z > 0.9999f && b > 100.0f) z = fminf(z, 1.0f - a / b);
    return z;
}

__global__ __launch_bounds__(256, 7) void lund_weight_kernel(
    const float4* __restrict__ Z4,     // (B,800) float4 view of (B,128,25)
    const float*  __restrict__ MT,     // (B,128)
    const int*    __restrict__ OBS,    // (B,2) int32, [:,0] = mult
    const float*  __restrict__ p_a,
    const float*  __restrict__ p_b,
    const float*  __restrict__ p_base,
    float* __restrict__ out)           // (B,)
{
    __shared__ float4 sK[128];      // {be2P, C2P, be20, C20} per m (log2 domain)
    __shared__ float2 sZM[3200];    // compacted {z, meta-as-float-bits}
    __shared__ int    sCnt;
    __shared__ float  sRed[8];

    const int b    = blockIdx.x;
    const int tid  = threadIdx.x;
    const int lane = tid & 31;
    if (tid == 0) sCnt = 0;

    const float aP = p_a[0],    bP = p_b[0];
    const float a0 = p_base[0], b0 = p_base[1];
    const float aUP = (aP < 0.02f) ? 0.0f : aP;   // plain `a` coefficient on lg2 terms
    const float aU0 = (a0 < 0.02f) ? 0.0f : a0;

    const int mult = OBS[b * 2];             // 20..128

    // ---- Phase 1: per-m constants (both sets), f2(z) = f(z)*LOG2E form:
    //      f2 = C2 - be2/z - lg2(z) + aU*lg2(1-z),  be2 = b_exp*LOG2E,
    //      C2 = be2/zmax + lg2(zmax) - aU*lg2(1-zmax).
    if (tid < 128) {
        const float mt  = MT[b * 128 + tid];
        const float mt2 = mt * mt;

        const float beP  = bP * mt2;
        const float zmP  = zmax_calc(aP, beP);
        const float be2P = beP * LOG2E;
        float C2P = be2P * rcp_fast(zmP) + lg2_fast(zmP);
        if (aUP != 0.0f) C2P -= aUP * lg2_fast(1.0f - zmP);

        const float be0  = b0 * mt2;
        const float zm0  = zmax_calc(a0, be0);
        const float be20 = be0 * LOG2E;
        float C20 = be20 * rcp_fast(zm0) + lg2_fast(zm0);
        if (aU0 != 0.0f) C20 -= aU0 * lg2_fast(1.0f - zm0);

        sK[tid] = make_float4(be2P, C2P, be20, C20);
    }
    __syncthreads();

    // ---- Phase 2: scan only the valid region (first mult*25 floats; all beyond
    //      are exactly zero, so quad over-read inside the row is harmless) ----
    const float4* __restrict__ zr = Z4 + (size_t)b * 800;
    const int nq    = (mult * 25 + 3) >> 2;
    const int iters = (nq + 255) >> 8;

    #pragma unroll 1
    for (int k = 0; k < iters; ++k) {
        const int g = tid + (k << 8);
        float4 v = make_float4(0.f, 0.f, 0.f, 0.f);
        if (g < nq) v = zr[g];

        const int c0 = (v.x != 0.f), c1 = (v.y != 0.f);
        const int c2 = (v.z != 0.f), c3 = (v.w != 0.f);
        const int c  = c0 + c1 + c2 + c3;

        int inc = c;                                    // warp-inclusive prefix sum
        #pragma unroll
        for (int off = 1; off < 32; off <<= 1) {
            int t = __shfl_up_sync(0xffffffffu, inc, off);
            if (lane >= off) inc += t;
        }
        int base;
        if (lane == 31) base = atomicAdd(&sCnt, inc);
        base = __shfl_sync(0xffffffffu, base, 31);
        int pos = base + inc - c;

        const int idx0 = g << 2;
        #pragma unroll
        for (int j = 0; j < 4; ++j) {
            const float zj = (j == 0) ? v.x : (j == 1) ? v.y : (j == 2) ? v.z : v.w;
            if (zj != 0.f) {
                const int idx  = idx0 + j;
                const int m    = (idx * 5243) >> 17;     // exact idx/25 for idx<3200
                const int accq = (idx - m * 25) == 0;
                sZM[pos] = make_float2(zj, __int_as_float(m | (accq << 15)));
                ++pos;
            }
        }
    }
    __syncthreads();
    const int n = sCnt;

    // ---- Phase 3: dense math over active elements ----
    float prod = 1.0f;
    #pragma unroll 1
    for (int i = tid; i < n; i += 256) {
        const float2 p    = sZM[i];
        const int    meta = __float_as_int(p.y);
        const float4 kk   = sK[meta & 127];
        const float  z    = p.x;

        const float rz  = rcp_fast(z);
        const float l2z = lg2_fast(z);
        const float l2o = lg2_fast(1.0f - z);

        float fP = fmaf(-kk.x, rz, kk.y);
        fP = fmaf(aUP, l2o, fP - l2z);
        float f0 = fmaf(-kk.z, rz, kk.w);
        f0 = fmaf(aU0, l2o, f0 - l2z);
        // f <= 0 by construction (zmax is the argmax) => only the lower clip binds
        fP = fmaxf(fP, F2MIN);
        f0 = fmaxf(f0, F2MIN);
        const float eP = ex2_fast(fP);
        const float e0 = ex2_fast(f0);

        const bool rej = (meta & 0x8000) == 0;
        const float num = rej ? (OSF - eP) : eP;
        const float den = rej ? (OSF - e0) : e0;
        prod *= num * rcp_fast(den);
    }

    // ---- Phase 4: block product reduction ----
    #pragma unroll
    for (int off = 16; off; off >>= 1)
        prod *= __shfl_xor_sync(0xffffffffu, prod, off);
    if (lane == 0) sRed[tid >> 5] = prod;
    __syncthreads();
    if (tid < 32) {
        float pr = (tid < 8) ? sRed[tid] : 1.0f;
        #pragma unroll
        for (int off = 4; off; off >>= 1)
            pr *= __shfl_xor_sync(0xffffffffu, pr, off);
        if (tid == 0) out[b] = pr;
    }
}

extern "C" void kernel_launch(void* const* d_in, const int* in_sizes, int n_in,
                              void* d_out, int out_size) {
    const float4* Z4     = (const float4*)d_in[0];
    const float*  MT     = (const float*)d_in[1];
    const int*    OBS    = (const int*)d_in[2];   // int32 on device (JAX x64-off downcast)
    const float*  p_a    = (const float*)d_in[3];
    const float*  p_b    = (const float*)d_in[4];
    const float*  p_base = (const float*)d_in[5];
    float* out = (float*)d_out;

    const int B = out_size;   // 8192
    lund_weight_kernel<<<B, 256>>>(Z4, MT, OBS, p_a, p_b, p_base, out);
}

// round 6
// speedup vs baseline: 1.6906x; 1.0077x over previous
#include <cuda_runtime.h>
#include <math.h>

// LundWeight reweighting, round 6: wide scan (8 elem/thread/iter), phase-1 on
// full block. Dense log2-domain math unchanged from the passing R5 kernel.
// z (8192,128,25) f32; mT (8192,128) f32; observable (8192,2) i32 (mult=[:,0]);
// params. Output (8192,) f32.

#define LOG2E 1.4426950408889634f
#define F2MIN (-72.13475f)  /* -50 * LOG2E */
#define OSF   15.0f

__device__ __forceinline__ float rcp_fast(float x){ float r; asm("rcp.approx.f32 %0,%1;":"=f"(r):"f"(x)); return r; }
__device__ __forceinline__ float lg2_fast(float x){ float r; asm("lg2.approx.f32 %0,%1;":"=f"(r):"f"(x)); return r; }
__device__ __forceinline__ float ex2_fast(float x){ float r; asm("ex2.approx.f32 %0,%1;":"=f"(r):"f"(x)); return r; }

__device__ __forceinline__ float zmax_calc(float a, float b) {
    const float c = 1.0f;
    if (a < 0.02f) return (c > b) ? b : 1.0f;
    if (fabsf(a - c) < 0.01f) return b / (b + c);
    float z = 0.5f * (b + c - sqrtf((b - c) * (b - c) + 4.0f * a * b)) / (c - a);
    if (z > 0.9999f && b > 100.0f) z = fminf(z, 1.0f - a / b);
    return z;
}

__global__ __launch_bounds__(256, 7) void lund_weight_kernel(
    const float4* __restrict__ Z4,     // (B,800) float4 view of (B,128,25)
    const float*  __restrict__ MT,     // (B,128)
    const int*    __restrict__ OBS,    // (B,2) int32, [:,0] = mult
    const float*  __restrict__ p_a,
    const float*  __restrict__ p_b,
    const float*  __restrict__ p_base,
    float* __restrict__ out)           // (B,)
{
    __shared__ float4 sK[128];      // {be2P, C2P, be20, C20} per m (log2 domain)
    __shared__ float2 sZM[3200];    // compacted {z, meta bits}
    __shared__ int    sCnt;
    __shared__ float  sRed[8];

    const int b    = blockIdx.x;
    const int tid  = threadIdx.x;
    const int lane = tid & 31;
    if (tid == 0) sCnt = 0;

    const float aP = p_a[0],    bP = p_b[0];
    const float a0 = p_base[0], b0 = p_base[1];
    const float aUP = (aP < 0.02f) ? 0.0f : aP;
    const float aU0 = (a0 < 0.02f) ? 0.0f : a0;

    const int mult = OBS[b * 2];             // 20..128

    // ---- Phase 1: 256 threads = 2 param-sets x 128 m; log2-domain constants:
    //      f2 = C2 - be2/z - lg2 z + aU*lg2(1-z);  be2 = b_exp*LOG2E;
    //      C2 = be2/zmax + lg2 zmax - aU*lg2(1-zmax).
    {
        const int   set  = tid >> 7;          // 0 = fit, 1 = base
        const int   m    = tid & 127;
        const float a    = set ? a0  : aP;
        const float bpar = set ? b0  : bP;
        const float aU   = set ? aU0 : aUP;
        const float mt   = MT[b * 128 + m];
        const float be   = bpar * mt * mt;
        const float zm   = zmax_calc(a, be);
        const float be2  = be * LOG2E;
        float C2 = be2 * rcp_fast(zm) + lg2_fast(zm);
        if (aU != 0.0f) C2 -= aU * lg2_fast(1.0f - zm);
        float* sKf = (float*)sK;
        sKf[(m << 2) + (set << 1) + 0] = be2;
        sKf[(m << 2) + (set << 1) + 1] = C2;
    }
    __syncthreads();

    // ---- Phase 2: scan valid region only (first mult*25 floats; rest of the
    //      row is exactly zero so quad-granularity over-read is harmless).
    //      8 contiguous elements per thread per iteration -> <= 2 iterations. ----
    const float4* __restrict__ zr = Z4 + (size_t)b * 800;
    const int nq = (mult * 25 + 3) >> 2;     // quads in valid region (<= 800)

    #pragma unroll 1
    for (int k = 0; k < 2; ++k) {
        if ((k << 9) >= nq) break;           // uniform per block
        const int q0 = (tid << 1) + (k << 9);
        float4 v0 = make_float4(0.f,0.f,0.f,0.f);
        float4 v1 = make_float4(0.f,0.f,0.f,0.f);
        if (q0     < nq) v0 = zr[q0];
        if (q0 + 1 < nq) v1 = zr[q0 + 1];

        const float vals[8] = {v0.x, v0.y, v0.z, v0.w, v1.x, v1.y, v1.z, v1.w};
        int c = 0;
        #pragma unroll
        for (int j = 0; j < 8; ++j) c += (vals[j] != 0.f);

        int inc = c;                                   // warp-inclusive prefix
        #pragma unroll
        for (int off = 1; off < 32; off <<= 1) {
            int t = __shfl_up_sync(0xffffffffu, inc, off);
            if (lane >= off) inc += t;
        }
        int base;
        if (lane == 31) base = atomicAdd(&sCnt, inc);  // lane31 inc == warp total
        base = __shfl_sync(0xffffffffu, base, 31);
        int pos = base + inc - c;

        const int idx0 = q0 << 2;                      // 8 contiguous idx from here
        #pragma unroll
        for (int j = 0; j < 8; ++j) {
            if (vals[j] != 0.f) {
                const int idx  = idx0 + j;
                const int m    = (idx * 5243) >> 17;   // exact idx/25, idx<3200
                const int accq = (idx - m * 25) == 0;
                sZM[pos] = make_float2(vals[j], __int_as_float(m | (accq << 15)));
                ++pos;
            }
        }
    }
    __syncthreads();
    const int n = sCnt;

    // ---- Phase 3: dense math over active elements ----
    float prod = 1.0f;
    #pragma unroll 1
    for (int i = tid; i < n; i += 256) {
        const float2 p    = sZM[i];
        const int    meta = __float_as_int(p.y);
        const float4 kk   = sK[meta & 127];
        const float  z    = p.x;

        const float rz  = rcp_fast(z);
        const float l2z = lg2_fast(z);
        const float l2o = lg2_fast(1.0f - z);

        float fP = fmaf(-kk.x, rz, kk.y);
        fP = fmaf(aUP, l2o, fP - l2z);
        float f0 = fmaf(-kk.z, rz, kk.w);
        f0 = fmaf(aU0, l2o, f0 - l2z);
        fP = fmaxf(fP, F2MIN);                // f <= 0 by construction; lower clip only
        f0 = fmaxf(f0, F2MIN);
        const float eP = ex2_fast(fP);
        const float e0 = ex2_fast(f0);

        const bool rej = (meta & 0x8000) == 0;
        const float num = rej ? (OSF - eP) : eP;
        const float den = rej ? (OSF - e0) : e0;
        prod *= num * rcp_fast(den);
    }

    // ---- Phase 4: block product reduction ----
    #pragma unroll
    for (int off = 16; off; off >>= 1)
        prod *= __shfl_xor_sync(0xffffffffu, prod, off);
    if (lane == 0) sRed[tid >> 5] = prod;
    __syncthreads();
    if (tid < 32) {
        float pr = (tid < 8) ? sRed[tid] : 1.0f;
        #pragma unroll
        for (int off = 4; off; off >>= 1)
            pr *= __shfl_xor_sync(0xffffffffu, pr, off);
        if (tid == 0) out[b] = pr;
    }
}

extern "C" void kernel_launch(void* const* d_in, const int* in_sizes, int n_in,
                              void* d_out, int out_size) {
    const float4* Z4     = (const float4*)d_in[0];
    const float*  MT     = (const float*)d_in[1];
    const int*    OBS    = (const int*)d_in[2];   // int32 on device
    const float*  p_a    = (const float*)d_in[3];
    const float*  p_b    = (const float*)d_in[4];
    const float*  p_base = (const float*)d_in[5];
    float* out = (float*)d_out;

    const int B = out_size;   // 8192
    lund_weight_kernel<<<B, 256>>>(Z4, MT, OBS, p_a, p_b, p_base, out);
}

// round 7
// speedup vs baseline: 1.9864x; 1.1750x over previous
#include <cuda_runtime.h>
#include <math.h>

// LundWeight reweighting, round 7: branch-free compaction scan.
//  - unconditional STS with dump-slot select (no BSSY/BSYNC, no divergence)
//  - per-thread shared atomicAdd replaces the 5-step shfl prefix chain
//  - meta (m, accq) decoded in the dense loop, not the scan
// z (8192,128,25) f32; mT (8192,128) f32; observable (8192,2) i32 (mult=[:,0]).
// Output (8192,) f32.

#define LOG2E 1.4426950408889634f
#define F2MIN (-72.13475f)  /* -50 * LOG2E */
#define OSF   15.0f

__device__ __forceinline__ float rcp_fast(float x){ float r; asm("rcp.approx.f32 %0,%1;":"=f"(r):"f"(x)); return r; }
__device__ __forceinline__ float lg2_fast(float x){ float r; asm("lg2.approx.f32 %0,%1;":"=f"(r):"f"(x)); return r; }
__device__ __forceinline__ float ex2_fast(float x){ float r; asm("ex2.approx.f32 %0,%1;":"=f"(r):"f"(x)); return r; }

__device__ __forceinline__ float zmax_calc(float a, float b) {
    const float c = 1.0f;
    if (a < 0.02f) return (c > b) ? b : 1.0f;
    if (fabsf(a - c) < 0.01f) return b / (b + c);
    float z = 0.5f * (b + c - sqrtf((b - c) * (b - c) + 4.0f * a * b)) / (c - a);
    if (z > 0.9999f && b > 100.0f) z = fminf(z, 1.0f - a / b);
    return z;
}

__global__ __launch_bounds__(256, 7) void lund_weight_kernel(
    const float4* __restrict__ Z4,     // (B,800) float4 view of (B,128,25)
    const float*  __restrict__ MT,     // (B,128)
    const int*    __restrict__ OBS,    // (B,2) int32, [:,0] = mult
    const float*  __restrict__ p_a,
    const float*  __restrict__ p_b,
    const float*  __restrict__ p_base,
    float* __restrict__ out)           // (B,)
{
    __shared__ float4 sK[128];      // {be2P, C2P, be20, C20} per m (log2 domain)
    __shared__ float2 sZM[3201];    // compacted {z, idx bits}; [3200] = dump slot
    __shared__ int    sCnt;
    __shared__ float  sRed[8];

    const int b    = blockIdx.x;
    const int tid  = threadIdx.x;
    const int lane = tid & 31;
    if (tid == 0) sCnt = 0;

    const float aP = p_a[0],    bP = p_b[0];
    const float a0 = p_base[0], b0 = p_base[1];
    const float aUP = (aP < 0.02f) ? 0.0f : aP;
    const float aU0 = (a0 < 0.02f) ? 0.0f : a0;

    const int mult = OBS[b * 2];             // 20..128

    // ---- Phase 1: 256 threads = 2 param-sets x 128 m; log2-domain constants:
    //      f2 = C2 - be2/z - lg2 z + aU*lg2(1-z);  be2 = b_exp*LOG2E;
    //      C2 = be2/zmax + lg2 zmax - aU*lg2(1-zmax).
    {
        const int   set  = tid >> 7;
        const int   m    = tid & 127;
        const float a    = set ? a0  : aP;
        const float bpar = set ? b0  : bP;
        const float aU   = set ? aU0 : aUP;
        const float mt   = MT[b * 128 + m];
        const float be   = bpar * mt * mt;
        const float zm   = zmax_calc(a, be);
        const float be2  = be * LOG2E;
        float C2 = be2 * rcp_fast(zm) + lg2_fast(zm);
        if (aU != 0.0f) C2 -= aU * lg2_fast(1.0f - zm);
        float* sKf = (float*)sK;
        sKf[(m << 2) + (set << 1) + 0] = be2;
        sKf[(m << 2) + (set << 1) + 1] = C2;
    }
    __syncthreads();

    // ---- Phase 2: branch-free compaction of the valid region (first mult*25
    //      floats; beyond that the row is exactly zero, so quad over-read is inert) ----
    const float4* __restrict__ zr = Z4 + (size_t)b * 800;
    const int nq = (mult * 25 + 3) >> 2;     // quads in valid region (<= 800)

    #pragma unroll 1
    for (int k = 0; k < 2; ++k) {
        if ((k << 9) >= nq) break;           // uniform across block
        const int q0 = (tid << 1) + (k << 9);
        float4 v0 = make_float4(0.f,0.f,0.f,0.f);
        float4 v1 = make_float4(0.f,0.f,0.f,0.f);
        if (q0     < nq) v0 = zr[q0];
        if (q0 + 1 < nq) v1 = zr[q0 + 1];

        const float vals[8] = {v0.x, v0.y, v0.z, v0.w, v1.x, v1.y, v1.z, v1.w};
        int c = 0;
        #pragma unroll
        for (int j = 0; j < 8; ++j) c += (vals[j] != 0.f);

        int pos = atomicAdd(&sCnt, c);       // 1 issued instr; LSU serializes lanes

        const int idx0 = q0 << 2;
        #pragma unroll
        for (int j = 0; j < 8; ++j) {
            const int act = (vals[j] != 0.f);
            const int dst = act ? pos : 3200;              // dump slot if inactive
            sZM[dst] = make_float2(vals[j], __int_as_float(idx0 + j));
            pos += act;
        }
    }
    __syncthreads();
    const int n = sCnt;

    // ---- Phase 3: dense math over active elements (meta decoded here) ----
    float prod = 1.0f;
    #pragma unroll 1
    for (int i = tid; i < n; i += 256) {
        const float2 p   = sZM[i];
        const int    idx = __float_as_int(p.y);
        const int    m   = (idx * 5243) >> 17;   // exact idx/25 for idx<3200
        const bool   rej = (idx - m * 25) != 0;  // r != 0 -> rejected-emission weight
        const float4 kk  = sK[m];
        const float  z   = p.x;

        const float rz  = rcp_fast(z);
        const float l2z = lg2_fast(z);
        const float l2o = lg2_fast(1.0f - z);

        float fP = fmaf(-kk.x, rz, kk.y);
        fP = fmaf(aUP, l2o, fP - l2z);
        float f0 = fmaf(-kk.z, rz, kk.w);
        f0 = fmaf(aU0, l2o, f0 - l2z);
        fP = fmaxf(fP, F2MIN);                // f <= 0 by construction; lower clip only
        f0 = fmaxf(f0, F2MIN);
        const float eP = ex2_fast(fP);
        const float e0 = ex2_fast(f0);

        const float num = rej ? (OSF - eP) : eP;
        const float den = rej ? (OSF - e0) : e0;
        prod *= num * rcp_fast(den);
    }

    // ---- Phase 4: block product reduction ----
    #pragma unroll
    for (int off = 16; off; off >>= 1)
        prod *= __shfl_xor_sync(0xffffffffu, prod, off);
    if (lane == 0) sRed[tid >> 5] = prod;
    __syncthreads();
    if (tid < 32) {
        float pr = (tid < 8) ? sRed[tid] : 1.0f;
        #pragma unroll
        for (int off = 4; off; off >>= 1)
            pr *= __shfl_xor_sync(0xffffffffu, pr, off);
        if (tid == 0) out[b] = pr;
    }
}

extern "C" void kernel_launch(void* const* d_in, const int* in_sizes, int n_in,
                              void* d_out, int out_size) {
    const float4* Z4     = (const float4*)d_in[0];
    const float*  MT     = (const float*)d_in[1];
    const int*    OBS    = (const int*)d_in[2];   // int32 on device
    const float*  p_a    = (const float*)d_in[3];
    const float*  p_b    = (const float*)d_in[4];
    const float*  p_base = (const float*)d_in[5];
    float* out = (float*)d_out;

    const int B = out_size;   // 8192
    lund_weight_kernel<<<B, 256>>>(Z4, MT, OBS, p_a, p_b, p_base, out);
}